// round 9
// baseline (speedup 1.0000x reference)
#include <cuda_runtime.h>
#include <math.h>

#define HW   4096
#define NC1  32
#define NC2  64
#define NFC1 512

// ---------------- scratch (static __device__, no allocation) ----------------
__device__ float  d_M1[NC1 * HW];                      // |FFT2(pad(w1))|   0.5 MB
__device__ float  d_A2[NC2 * HW];                      // layer-2 magnitude   1 MB
__device__ float  d_H[10 * HW];                        // fc2-collapsed     160 KB
__device__ float  d_biasv[10];                         // fc2b + fc2w@fc1b

// ---------------- L0 prep: M1 DFT + bias + zero H + zero out ----------------
// blocks [0,512): M1   512: bias   [513,523): zero H   523: zero out
__global__ void __launch_bounds__(256) k_prep(const float* __restrict__ w1r,
                                              const float* __restrict__ w1i,
                                              const float* __restrict__ fc2w,
                                              const float* __restrict__ fc1b,
                                              const float* __restrict__ fc2b,
                                              float* __restrict__ out) {
    __shared__ float twr[64], twi[64], wr[25], wi[25];
    const int bx = blockIdx.x;
    const int tx = threadIdx.x;
    if (bx < 512) {
        if (tx < 64) {
            float s, c;
            sincosf(-6.283185307179586f * (float)tx / 64.0f, &s, &c);
            twr[tx] = c; twi[tx] = s;
        }
        const int i = bx >> 4, tile = bx & 15;
        if (tx < 25) { wr[tx] = w1r[i * 25 + tx]; wi[tx] = w1i[i * 25 + tx]; }
        __syncthreads();
        const int hw = tile * 256 + tx;
        const int u = hw >> 6, v = hw & 63;
        float re = 0.f, im = 0.f;
#pragma unroll
        for (int a = 0; a < 5; a++)
#pragma unroll
            for (int b = 0; b < 5; b++) {
                const int idx = (u * a + v * b) & 63;
                const float tr = twr[idx], ti = twi[idx];
                const float r = wr[a * 5 + b], q = wi[a * 5 + b];
                re += r * tr - q * ti;
                im += r * ti + q * tr;
            }
        d_M1[i * HW + hw] = sqrtf(re * re + im * im);
    } else if (bx == 512) {
        // ---- bias: d_biasv[c] = fc2b[c] + sum_f fc2w[c,f]*fc1b[f] ----
        const int w = tx >> 5, lane = tx & 31;
        for (int c = w; c < 10; c += 8) {
            float s = 0.f;
            for (int f = lane; f < NFC1; f += 32)
                s += fc2w[c * NFC1 + f] * fc1b[f];
#pragma unroll
            for (int off = 16; off > 0; off >>= 1)
                s += __shfl_down_sync(0xffffffffu, s, off);
            if (lane == 0) d_biasv[c] = s + fc2b[c];
        }
    } else if (bx < 523) {
        const int base = (bx - 513) * 4096;
#pragma unroll
        for (int k = 0; k < 16; k++) d_H[base + k * 256 + tx] = 0.f;
    } else {
        for (int i = tx; i < 320; i += 256) out[i] = 0.f;
    }
}

// ---------------- L1: A2 via 4-fold twiddle symmetry, T computed in-block ---
// A2[o,hw] = |sum_i M1[i,hw] * sum_a tw(ua) * (sum_b w2c[o,i,a,b] tw(vb))|
__global__ void __launch_bounds__(256) k_a2f(const float* __restrict__ w2r,
                                             const float* __restrict__ w2i) {
    __shared__ float2 Ts[8 * 320];                // 8 i x 5 a x 64 v  (20 KB)
    __shared__ float twr[64], twi[64];
    const int tx = threadIdx.x;
    const int o = blockIdx.y;
    const int du = tx >> 6, v = tx & 63;
    const int u0 = blockIdx.x * 4 + du;           // in [0,16)
    if (tx < 64) {
        float s, c;
        sincosf(-6.283185307179586f * (float)tx / 64.0f, &s, &c);
        twr[tx] = c; twi[tx] = s;
    }
    __syncthreads();
    float tur[5], tui[5];
#pragma unroll
    for (int a = 0; a < 5; a++) {
        const int k = (u0 * a) & 63;
        tur[a] = twr[k]; tui[a] = twi[k];
    }
    float re0 = 0.f, im0 = 0.f, re1 = 0.f, im1 = 0.f;
    float re2 = 0.f, im2 = 0.f, re3 = 0.f, im3 = 0.f;
    const int hwb = u0 * 64 + v;

    for (int c = 0; c < 4; c++) {                 // i-chunks of 8
        __syncthreads();
        // ---- compute T for this chunk's 8 i's directly from w2 ----
        for (int idx = tx; idx < 8 * 320; idx += 256) {
            const int ii = idx / 320;
            const int r = idx - ii * 320;
            const int a = r >> 6, vv = r & 63;
            const int oi = o * NC1 + c * 8 + ii;
            float re = 0.f, im = 0.f;
#pragma unroll
            for (int b = 0; b < 5; b++) {
                const int k = (vv * b) & 63;
                const float rr = w2r[oi * 25 + a * 5 + b];
                const float qq = w2i[oi * 25 + a * 5 + b];
                re += rr * twr[k] - qq * twi[k];
                im += rr * twi[k] + qq * twr[k];
            }
            Ts[idx] = make_float2(re, im);
        }
        __syncthreads();
#pragma unroll
        for (int ii = 0; ii < 8; ii++) {
            const int ig = c * 8 + ii;
            const float m0 = d_M1[ig * HW + hwb];
            const float m1 = d_M1[ig * HW + hwb + 1024];
            const float m2 = d_M1[ig * HW + hwb + 2048];
            const float m3 = d_M1[ig * HW + hwb + 3072];
            float kr0 = 0.f, ki0 = 0.f, kr1 = 0.f, ki1 = 0.f;
            float kr2 = 0.f, ki2 = 0.f, kr3 = 0.f, ki3 = 0.f;
#pragma unroll
            for (int a = 0; a < 5; a++) {
                const float2 tt = Ts[ii * 320 + a * 64 + v];
                const float pr = tur[a] * tt.x - tui[a] * tt.y;
                const float pi = tur[a] * tt.y + tui[a] * tt.x;
                kr0 += pr; ki0 += pi;
                switch (a & 3) {
                    case 0: kr1 += pr; ki1 += pi;
                            kr2 += pr; ki2 += pi;
                            kr3 += pr; ki3 += pi; break;
                    case 1: kr1 += pi; ki1 -= pr;
                            kr2 -= pr; ki2 -= pi;
                            kr3 -= pi; ki3 += pr; break;
                    case 2: kr1 -= pr; ki1 -= pi;
                            kr2 += pr; ki2 += pi;
                            kr3 -= pr; ki3 -= pi; break;
                    case 3: kr1 -= pi; ki1 += pr;
                            kr2 -= pr; ki2 -= pi;
                            kr3 += pi; ki3 -= pr; break;
                }
            }
            re0 += m0 * kr0; im0 += m0 * ki0;
            re1 += m1 * kr1; im1 += m1 * ki1;
            re2 += m2 * kr2; im2 += m2 * ki2;
            re3 += m3 * kr3; im3 += m3 * ki3;
        }
    }
    d_A2[o * HW + hwb]        = sqrtf(re0 * re0 + im0 * im0);
    d_A2[o * HW + hwb + 1024] = sqrtf(re1 * re1 + im1 * im1);
    d_A2[o * HW + hwb + 2048] = sqrtf(re2 * re2 + im2 * im2);
    d_A2[o * HW + hwb + 3072] = sqrtf(re3 * re3 + im3 * im3);
}

// ---------------- L2 (dominant): stream fc1_w — frozen best config ----------
__global__ void __launch_bounds__(128) k_g(const float* __restrict__ fc1w,
                                           const float* __restrict__ fc2w) {
    __shared__ float4 a2s[16 * 128];              // 16 o-rows x 512 hw = 32 KB
    __shared__ float fc2s[10][8];
    const int t = threadIdx.x;
    const int tile = blockIdx.x;                  // 8 tiles of 512 hw
    const int f0 = blockIdx.y * 8;                // 64 f-chunks of 8
    if (t < 80) {
        const int c = t >> 3, f = t & 7;
        fc2s[c][f] = fc2w[c * NFC1 + f0 + f];
    }
    const float4* __restrict__ a2g = (const float4*)d_A2;
    const float4* __restrict__ w = (const float4*)fc1w;

    float4 acc[8];
#pragma unroll
    for (int f = 0; f < 8; f++) acc[f] = make_float4(0.f, 0.f, 0.f, 0.f);

    for (int oc = 0; oc < 4; oc++) {
        __syncthreads();
        for (int idx = t; idx < 16 * 128; idx += 128) {
            const int o = idx >> 7, j = idx & 127;
            a2s[idx] = a2g[(oc * 16 + o) * 1024 + tile * 128 + j];
        }
        __syncthreads();
#pragma unroll
        for (int o = 0; o < 16; o++) {
            const float4 av = a2s[o * 128 + t];
            const size_t wb = (size_t)(oc * 16 + o) * 1024 + (size_t)tile * 128 + t;
#pragma unroll
            for (int f = 0; f < 8; f++) {
                const float4 wv = __ldcs(&w[(size_t)(f0 + f) * 65536 + wb]);
                acc[f].x += av.x * wv.x;
                acc[f].y += av.y * wv.y;
                acc[f].z += av.z * wv.z;
                acc[f].w += av.w * wv.w;
            }
        }
    }
    const int hwb = (tile * 128 + t) * 4;
#pragma unroll
    for (int c = 0; c < 10; c++) {
        float hx = 0.f, hy = 0.f, hz = 0.f, hww = 0.f;
#pragma unroll
        for (int f = 0; f < 8; f++) {
            const float s = fc2s[c][f];
            hx += s * acc[f].x;
            hy += s * acc[f].y;
            hz += s * acc[f].z;
            hww += s * acc[f].w;
        }
        float* Hp = &d_H[c * HW + hwb];
        atomicAdd(Hp + 0, hx);
        atomicAdd(Hp + 1, hy);
        atomicAdd(Hp + 2, hz);
        atomicAdd(Hp + 3, hww);
    }
}

// ---------------- L3: out[b,c] += sum_hw |x|*H, 8 hw-chunks per batch -------
__global__ void __launch_bounds__(256) k_out(const float* __restrict__ x,
                                             float* __restrict__ out) {
    const int b = blockIdx.y;
    const int chunk = blockIdx.x;                 // 8 chunks of 512 hw
    const int tx = threadIdx.x;                   // 256
    const int hw0 = chunk * 512;
    float acc[10];
#pragma unroll
    for (int c = 0; c < 10; c++) acc[c] = 0.f;
#pragma unroll
    for (int k = 0; k < 2; k++) {
        const int hw = hw0 + k * 256 + tx;
        const float a = fabsf(x[b * HW + hw]);
#pragma unroll
        for (int c = 0; c < 10; c++) acc[c] += a * d_H[c * HW + hw];
    }
    __shared__ float red[10][256];
#pragma unroll
    for (int c = 0; c < 10; c++) red[c][tx] = acc[c];
    __syncthreads();
    for (int s = 128; s > 0; s >>= 1) {
        if (tx < s) {
#pragma unroll
            for (int c = 0; c < 10; c++) red[c][tx] += red[c][tx + s];
        }
        __syncthreads();
    }
    if (tx < 10) {
        float v = red[tx][0];
        if (chunk == 0) v += d_biasv[tx];
        atomicAdd(&out[b * 10 + tx], v);
    }
}

// ---------------- launch -----------------------------------------------------
extern "C" void kernel_launch(void* const* d_in, const int* in_sizes, int n_in,
                              void* d_out, int out_size) {
    const float* x    = (const float*)d_in[0];
    const float* w1r  = (const float*)d_in[1];
    const float* w1i  = (const float*)d_in[2];
    const float* w2r  = (const float*)d_in[3];
    const float* w2i  = (const float*)d_in[4];
    const float* fc1w = (const float*)d_in[5];
    const float* fc1b = (const float*)d_in[6];
    const float* fc2w = (const float*)d_in[7];
    const float* fc2b = (const float*)d_in[8];
    float* out = (float*)d_out;

    k_prep<<<524, 256>>>(w1r, w1i, fc2w, fc1b, fc2b, out);   // 0
    k_a2f <<<dim3(4, 64), 256>>>(w2r, w2i);                   // 1
    k_g   <<<dim3(8, 64), 128>>>(fc1w, fc2w);                 // 2
    k_out <<<dim3(8, 32), 256>>>(x, out);                     // 3
}

// round 10
// speedup vs baseline: 1.0199x; 1.0199x over previous
#include <cuda_runtime.h>
#include <math.h>

#define HW   4096
#define NC1  32
#define NC2  64
#define NFC1 512

// ---------------- scratch (static __device__, no allocation) ----------------
__device__ float  d_M1[NC1 * HW];                      // |FFT2(pad(w1))|   0.5 MB
__device__ float  d_A2[NC2 * HW];                      // layer-2 magnitude   1 MB
__device__ float  d_H[10 * HW];                        // fc2-collapsed     160 KB
__device__ float  d_biasv[10];                         // fc2b + fc2w@fc1b

// ---------------- L0 prep: M1 DFT + bias + zero H + zero out ----------------
// blocks [0,512): M1   512: bias   [513,523): zero H   523: zero out
__global__ void __launch_bounds__(256) k_prep(const float* __restrict__ w1r,
                                              const float* __restrict__ w1i,
                                              const float* __restrict__ fc2w,
                                              const float* __restrict__ fc1b,
                                              const float* __restrict__ fc2b,
                                              float* __restrict__ out) {
    __shared__ float twr[64], twi[64], wr[25], wi[25];
    const int bx = blockIdx.x;
    const int tx = threadIdx.x;
    if (bx < 512) {
        if (tx < 64) {
            float s, c;
            sincosf(-6.283185307179586f * (float)tx / 64.0f, &s, &c);
            twr[tx] = c; twi[tx] = s;
        }
        const int i = bx >> 4, tile = bx & 15;
        if (tx < 25) { wr[tx] = w1r[i * 25 + tx]; wi[tx] = w1i[i * 25 + tx]; }
        __syncthreads();
        const int hw = tile * 256 + tx;
        const int u = hw >> 6, v = hw & 63;
        float re = 0.f, im = 0.f;
#pragma unroll
        for (int a = 0; a < 5; a++)
#pragma unroll
            for (int b = 0; b < 5; b++) {
                const int idx = (u * a + v * b) & 63;
                const float tr = twr[idx], ti = twi[idx];
                const float r = wr[a * 5 + b], q = wi[a * 5 + b];
                re += r * tr - q * ti;
                im += r * ti + q * tr;
            }
        d_M1[i * HW + hw] = sqrtf(re * re + im * im);
    } else if (bx == 512) {
        // ---- bias: d_biasv[c] = fc2b[c] + sum_f fc2w[c,f]*fc1b[f] ----
        const int w = tx >> 5, lane = tx & 31;
        for (int c = w; c < 10; c += 8) {
            float s = 0.f;
            for (int f = lane; f < NFC1; f += 32)
                s += fc2w[c * NFC1 + f] * fc1b[f];
#pragma unroll
            for (int off = 16; off > 0; off >>= 1)
                s += __shfl_down_sync(0xffffffffu, s, off);
            if (lane == 0) d_biasv[c] = s + fc2b[c];
        }
    } else if (bx < 523) {
        const int base = (bx - 513) * 4096;
#pragma unroll
        for (int k = 0; k < 16; k++) d_H[base + k * 256 + tx] = 0.f;
    } else {
        for (int i = tx; i < 320; i += 256) out[i] = 0.f;
    }
}

// ---------------- L1: A2 via 4-fold twiddle symmetry, T computed in-block ---
__global__ void __launch_bounds__(256) k_a2f(const float* __restrict__ w2r,
                                             const float* __restrict__ w2i) {
    __shared__ float2 Ts[8 * 320];                // 8 i x 5 a x 64 v  (20 KB)
    __shared__ float twr[64], twi[64];
    const int tx = threadIdx.x;
    const int o = blockIdx.y;
    const int du = tx >> 6, v = tx & 63;
    const int u0 = blockIdx.x * 4 + du;           // in [0,16)
    if (tx < 64) {
        float s, c;
        sincosf(-6.283185307179586f * (float)tx / 64.0f, &s, &c);
        twr[tx] = c; twi[tx] = s;
    }
    __syncthreads();
    float tur[5], tui[5];
#pragma unroll
    for (int a = 0; a < 5; a++) {
        const int k = (u0 * a) & 63;
        tur[a] = twr[k]; tui[a] = twi[k];
    }
    float re0 = 0.f, im0 = 0.f, re1 = 0.f, im1 = 0.f;
    float re2 = 0.f, im2 = 0.f, re3 = 0.f, im3 = 0.f;
    const int hwb = u0 * 64 + v;

    for (int c = 0; c < 4; c++) {                 // i-chunks of 8
        __syncthreads();
        for (int idx = tx; idx < 8 * 320; idx += 256) {
            const int ii = idx / 320;
            const int r = idx - ii * 320;
            const int a = r >> 6, vv = r & 63;
            const int oi = o * NC1 + c * 8 + ii;
            float re = 0.f, im = 0.f;
#pragma unroll
            for (int b = 0; b < 5; b++) {
                const int k = (vv * b) & 63;
                const float rr = w2r[oi * 25 + a * 5 + b];
                const float qq = w2i[oi * 25 + a * 5 + b];
                re += rr * twr[k] - qq * twi[k];
                im += rr * twi[k] + qq * twr[k];
            }
            Ts[idx] = make_float2(re, im);
        }
        __syncthreads();
#pragma unroll
        for (int ii = 0; ii < 8; ii++) {
            const int ig = c * 8 + ii;
            const float m0 = d_M1[ig * HW + hwb];
            const float m1 = d_M1[ig * HW + hwb + 1024];
            const float m2 = d_M1[ig * HW + hwb + 2048];
            const float m3 = d_M1[ig * HW + hwb + 3072];
            float kr0 = 0.f, ki0 = 0.f, kr1 = 0.f, ki1 = 0.f;
            float kr2 = 0.f, ki2 = 0.f, kr3 = 0.f, ki3 = 0.f;
#pragma unroll
            for (int a = 0; a < 5; a++) {
                const float2 tt = Ts[ii * 320 + a * 64 + v];
                const float pr = tur[a] * tt.x - tui[a] * tt.y;
                const float pi = tur[a] * tt.y + tui[a] * tt.x;
                kr0 += pr; ki0 += pi;
                switch (a & 3) {
                    case 0: kr1 += pr; ki1 += pi;
                            kr2 += pr; ki2 += pi;
                            kr3 += pr; ki3 += pi; break;
                    case 1: kr1 += pi; ki1 -= pr;
                            kr2 -= pr; ki2 -= pi;
                            kr3 -= pi; ki3 += pr; break;
                    case 2: kr1 -= pr; ki1 -= pi;
                            kr2 += pr; ki2 += pi;
                            kr3 -= pr; ki3 -= pi; break;
                    case 3: kr1 -= pi; ki1 += pr;
                            kr2 -= pr; ki2 -= pi;
                            kr3 += pi; ki3 -= pr; break;
                }
            }
            re0 += m0 * kr0; im0 += m0 * ki0;
            re1 += m1 * kr1; im1 += m1 * ki1;
            re2 += m2 * kr2; im2 += m2 * ki2;
            re3 += m3 * kr3; im3 += m3 * ki3;
        }
    }
    d_A2[o * HW + hwb]        = sqrtf(re0 * re0 + im0 * im0);
    d_A2[o * HW + hwb + 1024] = sqrtf(re1 * re1 + im1 * im1);
    d_A2[o * HW + hwb + 2048] = sqrtf(re2 * re2 + im2 * im2);
    d_A2[o * HW + hwb + 3072] = sqrtf(re3 * re3 + im3 * im3);
}

// ---------------- L2 (dominant): stream fc1_w; vector RED.128 epilogue ------
__global__ void __launch_bounds__(128) k_g(const float* __restrict__ fc1w,
                                           const float* __restrict__ fc2w) {
    __shared__ float4 a2s[16 * 128];              // 16 o-rows x 512 hw = 32 KB
    __shared__ float fc2s[10][8];
    const int t = threadIdx.x;
    const int tile = blockIdx.x;                  // 8 tiles of 512 hw
    const int f0 = blockIdx.y * 8;                // 64 f-chunks of 8
    if (t < 80) {
        const int c = t >> 3, f = t & 7;
        fc2s[c][f] = fc2w[c * NFC1 + f0 + f];
    }
    const float4* __restrict__ a2g = (const float4*)d_A2;
    const float4* __restrict__ w = (const float4*)fc1w;

    float4 acc[8];
#pragma unroll
    for (int f = 0; f < 8; f++) acc[f] = make_float4(0.f, 0.f, 0.f, 0.f);

    for (int oc = 0; oc < 4; oc++) {
        __syncthreads();
        for (int idx = t; idx < 16 * 128; idx += 128) {
            const int o = idx >> 7, j = idx & 127;
            a2s[idx] = a2g[(oc * 16 + o) * 1024 + tile * 128 + j];
        }
        __syncthreads();
#pragma unroll
        for (int o = 0; o < 16; o++) {
            const float4 av = a2s[o * 128 + t];
            const size_t wb = (size_t)(oc * 16 + o) * 1024 + (size_t)tile * 128 + t;
#pragma unroll
            for (int f = 0; f < 8; f++) {
                const float4 wv = __ldcs(&w[(size_t)(f0 + f) * 65536 + wb]);
                acc[f].x += av.x * wv.x;
                acc[f].y += av.y * wv.y;
                acc[f].z += av.z * wv.z;
                acc[f].w += av.w * wv.w;
            }
        }
    }
    // epilogue: one 128-bit vector atomic per class (sm_90+ native float4 red)
    const int hwb = (tile * 128 + t) * 4;
#pragma unroll
    for (int c = 0; c < 10; c++) {
        float4 h = make_float4(0.f, 0.f, 0.f, 0.f);
#pragma unroll
        for (int f = 0; f < 8; f++) {
            const float s = fc2s[c][f];
            h.x += s * acc[f].x;
            h.y += s * acc[f].y;
            h.z += s * acc[f].z;
            h.w += s * acc[f].w;
        }
        atomicAdd(reinterpret_cast<float4*>(&d_H[c * HW + hwb]), h);
    }
}

// ---------------- L3: out[b,c] += sum_hw |x|*H, 8 hw-chunks per batch -------
__global__ void __launch_bounds__(256) k_out(const float* __restrict__ x,
                                             float* __restrict__ out) {
    const int b = blockIdx.y;
    const int chunk = blockIdx.x;                 // 8 chunks of 512 hw
    const int tx = threadIdx.x;                   // 256
    const int hw0 = chunk * 512;
    float acc[10];
#pragma unroll
    for (int c = 0; c < 10; c++) acc[c] = 0.f;
#pragma unroll
    for (int k = 0; k < 2; k++) {
        const int hw = hw0 + k * 256 + tx;
        const float a = fabsf(x[b * HW + hw]);
#pragma unroll
        for (int c = 0; c < 10; c++) acc[c] += a * d_H[c * HW + hw];
    }
    __shared__ float red[10][256];
#pragma unroll
    for (int c = 0; c < 10; c++) red[c][tx] = acc[c];
    __syncthreads();
    for (int s = 128; s > 0; s >>= 1) {
        if (tx < s) {
#pragma unroll
            for (int c = 0; c < 10; c++) red[c][tx] += red[c][tx + s];
        }
        __syncthreads();
    }
    if (tx < 10) {
        float v = red[tx][0];
        if (chunk == 0) v += d_biasv[tx];
        atomicAdd(&out[b * 10 + tx], v);
    }
}

// ---------------- launch -----------------------------------------------------
extern "C" void kernel_launch(void* const* d_in, const int* in_sizes, int n_in,
                              void* d_out, int out_size) {
    const float* x    = (const float*)d_in[0];
    const float* w1r  = (const float*)d_in[1];
    const float* w1i  = (const float*)d_in[2];
    const float* w2r  = (const float*)d_in[3];
    const float* w2i  = (const float*)d_in[4];
    const float* fc1w = (const float*)d_in[5];
    const float* fc1b = (const float*)d_in[6];
    const float* fc2w = (const float*)d_in[7];
    const float* fc2b = (const float*)d_in[8];
    float* out = (float*)d_out;

    k_prep<<<524, 256>>>(w1r, w1i, fc2w, fc1b, fc2b, out);   // 0
    k_a2f <<<dim3(4, 64), 256>>>(w2r, w2i);                   // 1
    k_g   <<<dim3(8, 64), 128>>>(fc1w, fc2w);                 // 2
    k_out <<<dim3(8, 32), 256>>>(x, out);                     // 3
}